// round 12
// baseline (speedup 1.0000x reference)
#include <cuda_runtime.h>
#include <math.h>

#define D_INNER 8192
#define D_MODEL 4096
#define DT_RANK 8
#define D_STATE 16
#define XP_DIM  (DT_RANK + 2 * D_STATE)   // 40
#define KT_XP   1024

// Scratch
__device__ float g_x_conv[D_INNER];
__device__ float g_z_silu[D_INNER];
__device__ float g_xp[XP_DIM];
__device__ float g_y[D_INNER];

// ---------------------------------------------------------------------------
// Kernel 1a: x-branch of W_in GEMV (rows 0..8191) + conv/silu epilogue.
// Warp-per-row, 128thr. Blocks 0-31 zero out[0:4096]; block 0 zeroes g_xp.
// grid = 2048, default stream.
// ---------------------------------------------------------------------------
__global__ __launch_bounds__(128, 16) void k_win_x(
    const float* __restrict__ W_in,
    const float* __restrict__ x,
    const float* __restrict__ conv_buffer,
    const float* __restrict__ conv_w,
    const float* __restrict__ conv_b,
    float* __restrict__ out)
{
    const int tid  = threadIdx.x;
    const int lane = tid & 31;
    const int warp = tid >> 5;
    if (blockIdx.x < 32) out[blockIdx.x * 128 + tid] = 0.0f;
    if (blockIdx.x == 0 && tid < XP_DIM) g_xp[tid] = 0.0f;

    const int row = blockIdx.x * 4 + warp;
    const float4* w4 = (const float4*)(W_in + (size_t)row * D_MODEL);
    const float4* x4 = (const float4*)x;

    float acc0 = 0.0f, acc1 = 0.0f;
    #pragma unroll
    for (int i = lane; i < D_MODEL / 4; i += 64) {
        float4 wa = __ldcs(&w4[i]);
        float4 wb = __ldcs(&w4[i + 32]);
        float4 va = x4[i];
        float4 vb = x4[i + 32];
        acc0 = fmaf(wa.x, va.x, acc0); acc0 = fmaf(wa.y, va.y, acc0);
        acc0 = fmaf(wa.z, va.z, acc0); acc0 = fmaf(wa.w, va.w, acc0);
        acc1 = fmaf(wb.x, vb.x, acc1); acc1 = fmaf(wb.y, vb.y, acc1);
        acc1 = fmaf(wb.z, vb.z, acc1); acc1 = fmaf(wb.w, vb.w, acc1);
    }
    float acc = acc0 + acc1;
    #pragma unroll
    for (int o = 16; o; o >>= 1) acc += __shfl_xor_sync(0xffffffffu, acc, o);

    if (lane == 0) {
        float b1 = conv_buffer[row * 3 + 1];
        float b2 = conv_buffer[row * 3 + 2];
        float4 cw = ((const float4*)conv_w)[row];
        float s = fmaf(b1, cw.x, fmaf(b2, cw.y,
                   fmaf(acc, cw.z, fmaf(acc, cw.w, conv_b[row]))));
        g_x_conv[row] = s / (1.0f + expf(-s));
    }
}

// ---------------------------------------------------------------------------
// Kernel 1b: z-branch of W_in GEMV (rows 8192..16383) -> g_z_silu.
// grid = 2048, LOW-PRIORITY second stream (overlaps k_xp).
// ---------------------------------------------------------------------------
__global__ __launch_bounds__(128, 16) void k_win_z(
    const float* __restrict__ W_in,
    const float* __restrict__ x)
{
    const int tid  = threadIdx.x;
    const int lane = tid & 31;
    const int warp = tid >> 5;

    const int row = D_INNER + blockIdx.x * 4 + warp;
    const float4* w4 = (const float4*)(W_in + (size_t)row * D_MODEL);
    const float4* x4 = (const float4*)x;

    float acc0 = 0.0f, acc1 = 0.0f;
    #pragma unroll
    for (int i = lane; i < D_MODEL / 4; i += 64) {
        float4 wa = __ldcs(&w4[i]);
        float4 wb = __ldcs(&w4[i + 32]);
        float4 va = x4[i];
        float4 vb = x4[i + 32];
        acc0 = fmaf(wa.x, va.x, acc0); acc0 = fmaf(wa.y, va.y, acc0);
        acc0 = fmaf(wa.z, va.z, acc0); acc0 = fmaf(wa.w, va.w, acc0);
        acc1 = fmaf(wb.x, vb.x, acc1); acc1 = fmaf(wb.y, vb.y, acc1);
        acc1 = fmaf(wb.z, vb.z, acc1); acc1 = fmaf(wb.w, vb.w, acc1);
    }
    float acc = acc0 + acc1;
    #pragma unroll
    for (int o = 16; o; o >>= 1) acc += __shfl_xor_sync(0xffffffffu, acc, o);

    if (lane == 0)
        g_z_silu[row - D_INNER] = acc / (1.0f + expf(-acc));
}

// ---------------------------------------------------------------------------
// Kernel 2: xp = W_xp @ x_conv  (40 x 8192). Split-K grid (40, 8),
// atomicAdd into g_xp. Runs concurrent with k_win_z.
// ---------------------------------------------------------------------------
__global__ __launch_bounds__(256) void k_xp(const float* __restrict__ W_xp)
{
    __shared__ float red[8];
    const int row   = blockIdx.x;
    const int kbase = blockIdx.y * KT_XP;
    const int tid   = threadIdx.x;

    const float4* w4 = (const float4*)(W_xp + (size_t)row * D_INNER + kbase);
    const float4* v4 = (const float4*)(g_x_conv + kbase);

    float acc = 0.0f;
    #pragma unroll
    for (int i = tid; i < KT_XP / 4; i += 256) {
        float4 w = __ldcs(&w4[i]);
        float4 v = v4[i];
        acc = fmaf(w.x, v.x, acc);
        acc = fmaf(w.y, v.y, acc);
        acc = fmaf(w.z, v.z, acc);
        acc = fmaf(w.w, v.w, acc);
    }
    #pragma unroll
    for (int o = 16; o; o >>= 1) acc += __shfl_xor_sync(0xffffffffu, acc, o);
    const int warp = tid >> 5, lane = tid & 31;
    if (lane == 0) red[warp] = acc;
    __syncthreads();
    if (warp == 0) {
        float a = (lane < 8) ? red[lane] : 0.0f;
        #pragma unroll
        for (int o = 4; o; o >>= 1) a += __shfl_xor_sync(0xffffffffu, a, o);
        if (lane == 0) atomicAdd(&g_xp[row], a);
    }
}

// ---------------------------------------------------------------------------
// Kernel 3: per-channel SSM update (after join with z-stream).
// Writes new_h into d_out[4096:], y -> g_y.
// ---------------------------------------------------------------------------
__global__ __launch_bounds__(256) void k_ssm(
    const float* __restrict__ W_dt,
    const float* __restrict__ b_dt,
    const float* __restrict__ ssm_state,
    const float* __restrict__ A_log,
    const float* __restrict__ D_param,
    float* __restrict__ d_out)
{
    __shared__ float sxp[XP_DIM];
    const int tid = threadIdx.x;
    if (tid < XP_DIM) sxp[tid] = g_xp[tid];
    __syncthreads();

    const int ch = blockIdx.x * 256 + tid;

    float dtr = b_dt[ch];
    const float4* wd4 = (const float4*)(W_dt + (size_t)ch * DT_RANK);
    float4 w0 = wd4[0], w1 = wd4[1];
    dtr = fmaf(w0.x, sxp[0], dtr);
    dtr = fmaf(w0.y, sxp[1], dtr);
    dtr = fmaf(w0.z, sxp[2], dtr);
    dtr = fmaf(w0.w, sxp[3], dtr);
    dtr = fmaf(w1.x, sxp[4], dtr);
    dtr = fmaf(w1.y, sxp[5], dtr);
    dtr = fmaf(w1.z, sxp[6], dtr);
    dtr = fmaf(w1.w, sxp[7], dtr);
    float dt = (dtr > 20.0f) ? dtr : log1pf(expf(dtr));

    const float xc = g_x_conv[ch];
    const float* al = A_log + (size_t)ch * D_STATE;
    const float* st = ssm_state + (size_t)ch * D_STATE;
    float* hout = d_out + D_MODEL + (size_t)ch * D_STATE;

    float acc = 0.0f;
    #pragma unroll
    for (int s = 0; s < D_STATE; s++) {
        float A    = -expf(al[s]);
        float abar = expf(dt * A);
        float h    = fmaf(abar, st[s], dt * sxp[DT_RANK + s] * xc);
        hout[s] = h;
        acc = fmaf(h, sxp[DT_RANK + D_STATE + s], acc);
    }
    g_y[ch] = fmaf(D_param[ch], xc, acc) * g_z_silu[ch];
}

// ---------------------------------------------------------------------------
// Kernel 4: out = W_out @ y (4096 x 8192). Warp per (row, K-quarter),
// 8KB contiguous stream per warp. grid = 4096. atomicAdd (out zeroed
// by k_win_x).
// ---------------------------------------------------------------------------
__global__ __launch_bounds__(128, 16) void k_wout(
    const float* __restrict__ W_out,
    float* __restrict__ out)
{
    const int tid  = threadIdx.x;
    const int lane = tid & 31;
    const int g    = blockIdx.x * 4 + (tid >> 5);   // global warp id
    const int row  = g >> 2;
    const int kb4  = (g & 3) * (D_INNER / 16);      // quarter offset in float4s

    const float4* w4 = (const float4*)(W_out + (size_t)row * D_INNER) + kb4;
    const float4* y4 = (const float4*)g_y + kb4;

    float acc0 = 0.0f, acc1 = 0.0f;
    #pragma unroll
    for (int i = lane; i < D_INNER / 16; i += 64) {
        float4 wa = __ldcs(&w4[i]);
        float4 wb = __ldcs(&w4[i + 32]);
        float4 va = y4[i];
        float4 vb = y4[i + 32];
        acc0 = fmaf(wa.x, va.x, acc0); acc0 = fmaf(wa.y, va.y, acc0);
        acc0 = fmaf(wa.z, va.z, acc0); acc0 = fmaf(wa.w, va.w, acc0);
        acc1 = fmaf(wb.x, vb.x, acc1); acc1 = fmaf(wb.y, vb.y, acc1);
        acc1 = fmaf(wb.z, vb.z, acc1); acc1 = fmaf(wb.w, vb.w, acc1);
    }
    float acc = acc0 + acc1;
    #pragma unroll
    for (int o = 16; o; o >>= 1) acc += __shfl_xor_sync(0xffffffffu, acc, o);
    if (lane == 0) atomicAdd(&out[row], acc);
}

// ---------------------------------------------------------------------------
extern "C" void kernel_launch(void* const* d_in, const int* in_sizes, int n_in,
                              void* d_out, int out_size)
{
    const float* x           = (const float*)d_in[0];
    const float* ssm_state   = (const float*)d_in[1];
    const float* conv_buffer = (const float*)d_in[2];
    const float* W_in        = (const float*)d_in[3];
    const float* conv_w      = (const float*)d_in[4];
    const float* conv_b      = (const float*)d_in[5];
    const float* W_xp        = (const float*)d_in[6];
    const float* W_dt        = (const float*)d_in[7];
    const float* b_dt        = (const float*)d_in[8];
    const float* A_log       = (const float*)d_in[9];
    const float* D_param     = (const float*)d_in[10];
    const float* W_out       = (const float*)d_in[11];
    float* out = (float*)d_out;

    // Lazy one-time creation (first call is the uncaptured correctness run).
    static cudaStream_t s2 = nullptr;
    static cudaEvent_t  ev_fork = nullptr, ev_join = nullptr;
    if (s2 == nullptr) {
        int leastPrio = 0, greatestPrio = 0;
        cudaDeviceGetStreamPriorityRange(&leastPrio, &greatestPrio);
        cudaStreamCreateWithPriority(&s2, cudaStreamNonBlocking, leastPrio);
        cudaEventCreateWithFlags(&ev_fork, cudaEventDisableTiming);
        cudaEventCreateWithFlags(&ev_join, cudaEventDisableTiming);
    }

    // Fork: z-branch runs on low-priority s2, concurrent with x-branch + xp.
    cudaEventRecord(ev_fork, 0);
    cudaStreamWaitEvent(s2, ev_fork, 0);

    k_win_x<<<2048, 128>>>(W_in, x, conv_buffer, conv_w, conv_b, out);
    k_win_z<<<2048, 128, 0, s2>>>(W_in, x);

    k_xp<<<dim3(XP_DIM, D_INNER / KT_XP), 256>>>(W_xp);   // after k_win_x only

    // Join: ssm needs g_z_silu from s2.
    cudaEventRecord(ev_join, s2);
    cudaStreamWaitEvent(0, ev_join, 0);

    k_ssm <<<D_INNER / 256, 256>>>(W_dt, b_dt, ssm_state, A_log, D_param, out);
    k_wout<<<4096, 128>>>(W_out, out);
}

// round 13
// speedup vs baseline: 1.0840x; 1.0840x over previous
#include <cuda_runtime.h>
#include <math.h>

#define D_INNER 8192
#define D_MODEL 4096
#define DT_RANK 8
#define D_STATE 16
#define XP_DIM  (DT_RANK + 2 * D_STATE)   // 40
#define KT_XP   1024

// Scratch
__device__ float g_x_conv[D_INNER];
__device__ float g_z_silu[D_INNER];
__device__ float g_xp[XP_DIM];
__device__ float g_y[D_INNER];

// ---------------------------------------------------------------------------
// Kernel 1: xz = W_in @ x (16384 x 4096) + fused conv/silu epilogue.
// Warp-per-row, 128thr, 16 blocks/SM. Blocks 0-31 zero out[0:4096];
// block 0 zeroes g_xp. grid = 4096.
// ---------------------------------------------------------------------------
__global__ __launch_bounds__(128, 16) void k_win(
    const float* __restrict__ W_in,
    const float* __restrict__ x,
    const float* __restrict__ conv_buffer,
    const float* __restrict__ conv_w,
    const float* __restrict__ conv_b,
    float* __restrict__ out)
{
    const int tid  = threadIdx.x;
    const int lane = tid & 31;
    const int warp = tid >> 5;
    if (blockIdx.x < 32) out[blockIdx.x * 128 + tid] = 0.0f;
    if (blockIdx.x == 0 && tid < XP_DIM) g_xp[tid] = 0.0f;

    const int row = blockIdx.x * 4 + warp;
    const float4* w4 = (const float4*)(W_in + (size_t)row * D_MODEL);
    const float4* x4 = (const float4*)x;

    float acc0 = 0.0f, acc1 = 0.0f;
    #pragma unroll
    for (int i = lane; i < D_MODEL / 4; i += 64) {
        float4 wa = __ldcs(&w4[i]);
        float4 wb = __ldcs(&w4[i + 32]);
        float4 va = x4[i];
        float4 vb = x4[i + 32];
        acc0 = fmaf(wa.x, va.x, acc0); acc0 = fmaf(wa.y, va.y, acc0);
        acc0 = fmaf(wa.z, va.z, acc0); acc0 = fmaf(wa.w, va.w, acc0);
        acc1 = fmaf(wb.x, vb.x, acc1); acc1 = fmaf(wb.y, vb.y, acc1);
        acc1 = fmaf(wb.z, vb.z, acc1); acc1 = fmaf(wb.w, vb.w, acc1);
    }
    float acc = acc0 + acc1;
    #pragma unroll
    for (int o = 16; o; o >>= 1) acc += __shfl_xor_sync(0xffffffffu, acc, o);

    if (lane == 0) {
        if (row < D_INNER) {
            float b1 = conv_buffer[row * 3 + 1];
            float b2 = conv_buffer[row * 3 + 2];
            float4 cw = ((const float4*)conv_w)[row];
            float s = fmaf(b1, cw.x, fmaf(b2, cw.y,
                       fmaf(acc, cw.z, fmaf(acc, cw.w, conv_b[row]))));
            g_x_conv[row] = s / (1.0f + __expf(-s));
        } else {
            g_z_silu[row - D_INNER] = acc / (1.0f + __expf(-acc));
        }
    }
}

// ---------------------------------------------------------------------------
// Kernel 2: xp = W_xp @ x_conv  (40 x 8192). Split-K grid (40, 8),
// atomicAdd into g_xp.
// ---------------------------------------------------------------------------
__global__ __launch_bounds__(256) void k_xp(const float* __restrict__ W_xp)
{
    __shared__ float red[8];
    const int row   = blockIdx.x;
    const int kbase = blockIdx.y * KT_XP;
    const int tid   = threadIdx.x;

    const float4* w4 = (const float4*)(W_xp + (size_t)row * D_INNER + kbase);
    const float4* v4 = (const float4*)(g_x_conv + kbase);

    float acc = 0.0f;
    #pragma unroll
    for (int i = tid; i < KT_XP / 4; i += 256) {
        float4 w = __ldcs(&w4[i]);
        float4 v = v4[i];
        acc = fmaf(w.x, v.x, acc);
        acc = fmaf(w.y, v.y, acc);
        acc = fmaf(w.z, v.z, acc);
        acc = fmaf(w.w, v.w, acc);
    }
    #pragma unroll
    for (int o = 16; o; o >>= 1) acc += __shfl_xor_sync(0xffffffffu, acc, o);
    const int warp = tid >> 5, lane = tid & 31;
    if (lane == 0) red[warp] = acc;
    __syncthreads();
    if (warp == 0) {
        float a = (lane < 8) ? red[lane] : 0.0f;
        #pragma unroll
        for (int o = 4; o; o >>= 1) a += __shfl_xor_sync(0xffffffffu, a, o);
        if (lane == 0) atomicAdd(&g_xp[row], a);
    }
}

// ---------------------------------------------------------------------------
// Kernel 3: SSM update, 16 lanes per channel. thread t -> (ch = g/16,
// s = g%16). All loads coalesced; dt's rank-8 dot computed redundantly
// per lane from smem xp; y-reduction via 16-lane shuffle.
// grid = 512 x 256thr. Writes new_h into d_out[4096:], y -> g_y.
// ---------------------------------------------------------------------------
__global__ __launch_bounds__(256) void k_ssm(
    const float* __restrict__ W_dt,
    const float* __restrict__ b_dt,
    const float* __restrict__ ssm_state,
    const float* __restrict__ A_log,
    const float* __restrict__ D_param,
    float* __restrict__ d_out)
{
    __shared__ float sxp[XP_DIM];
    const int tid = threadIdx.x;
    if (tid < XP_DIM) sxp[tid] = g_xp[tid];
    __syncthreads();

    const int g  = blockIdx.x * 256 + tid;     // global lane id
    const int ch = g >> 4;                      // channel
    const int s  = g & 15;                      // state index

    // dt (same value across the 16 lanes of a channel)
    float dtr = b_dt[ch];
    const float4* wd4 = (const float4*)(W_dt + (size_t)ch * DT_RANK);
    float4 w0 = wd4[0], w1 = wd4[1];
    dtr = fmaf(w0.x, sxp[0], dtr); dtr = fmaf(w0.y, sxp[1], dtr);
    dtr = fmaf(w0.z, sxp[2], dtr); dtr = fmaf(w0.w, sxp[3], dtr);
    dtr = fmaf(w1.x, sxp[4], dtr); dtr = fmaf(w1.y, sxp[5], dtr);
    dtr = fmaf(w1.z, sxp[6], dtr); dtr = fmaf(w1.w, sxp[7], dtr);
    float dt = (dtr > 20.0f) ? dtr : log1pf(__expf(dtr));

    const float xc = g_x_conv[ch];

    // per-(ch, s) element — fully coalesced
    const int idx = ch * D_STATE + s;
    float A    = -__expf(A_log[idx]);
    float abar = __expf(dt * A);
    float h    = fmaf(abar, ssm_state[idx], dt * sxp[DT_RANK + s] * xc);
    d_out[D_MODEL + idx] = h;

    // y = sum_s h * C[s]  — reduce over the 16 lanes of this channel
    float part = h * sxp[DT_RANK + D_STATE + s];
    #pragma unroll
    for (int o = 8; o; o >>= 1) part += __shfl_xor_sync(0xffffffffu, part, o);
    if (s == 0)
        g_y[ch] = fmaf(D_param[ch], xc, part) * g_z_silu[ch];
}

// ---------------------------------------------------------------------------
// Kernel 4: out = W_out @ y (4096 x 8192). Warp per (row, K-quarter),
// 8KB contiguous stream per warp. grid = 4096. atomicAdd (out zeroed
// by k_win).
// ---------------------------------------------------------------------------
__global__ __launch_bounds__(128, 16) void k_wout(
    const float* __restrict__ W_out,
    float* __restrict__ out)
{
    const int tid  = threadIdx.x;
    const int lane = tid & 31;
    const int g    = blockIdx.x * 4 + (tid >> 5);   // global warp id
    const int row  = g >> 2;
    const int kb4  = (g & 3) * (D_INNER / 16);      // quarter offset in float4s

    const float4* w4 = (const float4*)(W_out + (size_t)row * D_INNER) + kb4;
    const float4* y4 = (const float4*)g_y + kb4;

    float acc0 = 0.0f, acc1 = 0.0f;
    #pragma unroll
    for (int i = lane; i < D_INNER / 16; i += 64) {
        float4 wa = __ldcs(&w4[i]);
        float4 wb = __ldcs(&w4[i + 32]);
        float4 va = y4[i];
        float4 vb = y4[i + 32];
        acc0 = fmaf(wa.x, va.x, acc0); acc0 = fmaf(wa.y, va.y, acc0);
        acc0 = fmaf(wa.z, va.z, acc0); acc0 = fmaf(wa.w, va.w, acc0);
        acc1 = fmaf(wb.x, vb.x, acc1); acc1 = fmaf(wb.y, vb.y, acc1);
        acc1 = fmaf(wb.z, vb.z, acc1); acc1 = fmaf(wb.w, vb.w, acc1);
    }
    float acc = acc0 + acc1;
    #pragma unroll
    for (int o = 16; o; o >>= 1) acc += __shfl_xor_sync(0xffffffffu, acc, o);
    if (lane == 0) atomicAdd(&out[row], acc);
}

// ---------------------------------------------------------------------------
extern "C" void kernel_launch(void* const* d_in, const int* in_sizes, int n_in,
                              void* d_out, int out_size)
{
    const float* x           = (const float*)d_in[0];
    const float* ssm_state   = (const float*)d_in[1];
    const float* conv_buffer = (const float*)d_in[2];
    const float* W_in        = (const float*)d_in[3];
    const float* conv_w      = (const float*)d_in[4];
    const float* conv_b      = (const float*)d_in[5];
    const float* W_xp        = (const float*)d_in[6];
    const float* W_dt        = (const float*)d_in[7];
    const float* b_dt        = (const float*)d_in[8];
    const float* A_log       = (const float*)d_in[9];
    const float* D_param     = (const float*)d_in[10];
    const float* W_out       = (const float*)d_in[11];
    float* out = (float*)d_out;

    k_win <<<4096, 128>>>(W_in, x, conv_buffer, conv_w, conv_b, out);
    k_xp  <<<dim3(XP_DIM, D_INNER / KT_XP), 256>>>(W_xp);
    k_ssm <<<(D_INNER * D_STATE) / 256, 256>>>(W_dt, b_dt, ssm_state, A_log,
                                               D_param, out);
    k_wout<<<4096, 128>>>(W_out, out);
}

// round 14
// speedup vs baseline: 1.0873x; 1.0031x over previous
#include <cuda_runtime.h>
#include <cuda_pipeline.h>
#include <math.h>

#define D_INNER 8192
#define D_MODEL 4096
#define DT_RANK 8
#define D_STATE 16
#define XP_DIM  (DT_RANK + 2 * D_STATE)   // 40
#define KT_XP   1024

// Scratch
__device__ float g_x_conv[D_INNER];
__device__ float g_z_silu[D_INNER];
__device__ float g_xp[XP_DIM];
__device__ float g_y[D_INNER];

// ---------------------------------------------------------------------------
// Kernel 1: xz = W_in @ x (16384 x 4096) + fused conv/silu epilogue.
// Warp-per-row, 128thr, 16 blocks/SM. Blocks 0-31 zero out[0:4096];
// block 0 zeroes g_xp. grid = 4096.  (UNCHANGED — at BW ceiling.)
// ---------------------------------------------------------------------------
__global__ __launch_bounds__(128, 16) void k_win(
    const float* __restrict__ W_in,
    const float* __restrict__ x,
    const float* __restrict__ conv_buffer,
    const float* __restrict__ conv_w,
    const float* __restrict__ conv_b,
    float* __restrict__ out)
{
    const int tid  = threadIdx.x;
    const int lane = tid & 31;
    const int warp = tid >> 5;
    if (blockIdx.x < 32) out[blockIdx.x * 128 + tid] = 0.0f;
    if (blockIdx.x == 0 && tid < XP_DIM) g_xp[tid] = 0.0f;

    const int row = blockIdx.x * 4 + warp;
    const float4* w4 = (const float4*)(W_in + (size_t)row * D_MODEL);
    const float4* x4 = (const float4*)x;

    float acc0 = 0.0f, acc1 = 0.0f;
    #pragma unroll
    for (int i = lane; i < D_MODEL / 4; i += 64) {
        float4 wa = __ldcs(&w4[i]);
        float4 wb = __ldcs(&w4[i + 32]);
        float4 va = x4[i];
        float4 vb = x4[i + 32];
        acc0 = fmaf(wa.x, va.x, acc0); acc0 = fmaf(wa.y, va.y, acc0);
        acc0 = fmaf(wa.z, va.z, acc0); acc0 = fmaf(wa.w, va.w, acc0);
        acc1 = fmaf(wb.x, vb.x, acc1); acc1 = fmaf(wb.y, vb.y, acc1);
        acc1 = fmaf(wb.z, vb.z, acc1); acc1 = fmaf(wb.w, vb.w, acc1);
    }
    float acc = acc0 + acc1;
    #pragma unroll
    for (int o = 16; o; o >>= 1) acc += __shfl_xor_sync(0xffffffffu, acc, o);

    if (lane == 0) {
        if (row < D_INNER) {
            float b1 = conv_buffer[row * 3 + 1];
            float b2 = conv_buffer[row * 3 + 2];
            float4 cw = ((const float4*)conv_w)[row];
            float s = fmaf(b1, cw.x, fmaf(b2, cw.y,
                       fmaf(acc, cw.z, fmaf(acc, cw.w, conv_b[row]))));
            g_x_conv[row] = s / (1.0f + __expf(-s));
        } else {
            g_z_silu[row - D_INNER] = acc / (1.0f + __expf(-acc));
        }
    }
}

// ---------------------------------------------------------------------------
// Kernel 2: xp = W_xp @ x_conv  (40 x 8192). Split-K grid (40, 8).
// ---------------------------------------------------------------------------
__global__ __launch_bounds__(256) void k_xp(const float* __restrict__ W_xp)
{
    __shared__ float red[8];
    const int row   = blockIdx.x;
    const int kbase = blockIdx.y * KT_XP;
    const int tid   = threadIdx.x;

    const float4* w4 = (const float4*)(W_xp + (size_t)row * D_INNER + kbase);
    const float4* v4 = (const float4*)(g_x_conv + kbase);

    float acc = 0.0f;
    #pragma unroll
    for (int i = tid; i < KT_XP / 4; i += 256) {
        float4 w = __ldcs(&w4[i]);
        float4 v = v4[i];
        acc = fmaf(w.x, v.x, acc);
        acc = fmaf(w.y, v.y, acc);
        acc = fmaf(w.z, v.z, acc);
        acc = fmaf(w.w, v.w, acc);
    }
    #pragma unroll
    for (int o = 16; o; o >>= 1) acc += __shfl_xor_sync(0xffffffffu, acc, o);
    const int warp = tid >> 5, lane = tid & 31;
    if (lane == 0) red[warp] = acc;
    __syncthreads();
    if (warp == 0) {
        float a = (lane < 8) ? red[lane] : 0.0f;
        #pragma unroll
        for (int o = 4; o; o >>= 1) a += __shfl_xor_sync(0xffffffffu, a, o);
        if (lane == 0) atomicAdd(&g_xp[row], a);
    }
}

// ---------------------------------------------------------------------------
// Kernel 3: SSM update, 16 lanes per channel (UNCHANGED from R13).
// ---------------------------------------------------------------------------
__global__ __launch_bounds__(256) void k_ssm(
    const float* __restrict__ W_dt,
    const float* __restrict__ b_dt,
    const float* __restrict__ ssm_state,
    const float* __restrict__ A_log,
    const float* __restrict__ D_param,
    float* __restrict__ d_out)
{
    __shared__ float sxp[XP_DIM];
    const int tid = threadIdx.x;
    if (tid < XP_DIM) sxp[tid] = g_xp[tid];
    __syncthreads();

    const int g  = blockIdx.x * 256 + tid;
    const int ch = g >> 4;
    const int s  = g & 15;

    float dtr = b_dt[ch];
    const float4* wd4 = (const float4*)(W_dt + (size_t)ch * DT_RANK);
    float4 w0 = wd4[0], w1 = wd4[1];
    dtr = fmaf(w0.x, sxp[0], dtr); dtr = fmaf(w0.y, sxp[1], dtr);
    dtr = fmaf(w0.z, sxp[2], dtr); dtr = fmaf(w0.w, sxp[3], dtr);
    dtr = fmaf(w1.x, sxp[4], dtr); dtr = fmaf(w1.y, sxp[5], dtr);
    dtr = fmaf(w1.z, sxp[6], dtr); dtr = fmaf(w1.w, sxp[7], dtr);
    float dt = (dtr > 20.0f) ? dtr : log1pf(__expf(dtr));

    const float xc = g_x_conv[ch];

    const int idx = ch * D_STATE + s;
    float A    = -__expf(A_log[idx]);
    float abar = __expf(dt * A);
    float h    = fmaf(abar, ssm_state[idx], dt * sxp[DT_RANK + s] * xc);
    d_out[D_MODEL + idx] = h;

    float part = h * sxp[DT_RANK + D_STATE + s];
    #pragma unroll
    for (int o = 8; o; o >>= 1) part += __shfl_xor_sync(0xffffffffu, part, o);
    if (s == 0)
        g_y[ch] = fmaf(D_param[ch], xc, part) * g_z_silu[ch];
}

// ---------------------------------------------------------------------------
// Kernel 4: out = W_out @ y. Warp per (row, K-quarter), but weights are
// streamed through a WARP-PRIVATE cp.async double buffer (no barriers):
// per-thread pipeline depth 2 chunks x 2 float4 -> 4 f4 in flight without
// register cost. Chunk = 64 f4 (2 f4/thread); 8 chunks per 512-f4 quarter.
// smem 8KB/block (2 bufs x 64 f4 x 4 warps) -> 128KB/SM at 16 blocks/SM.
// ---------------------------------------------------------------------------
__global__ __launch_bounds__(128, 16) void k_wout(
    const float* __restrict__ W_out,
    float* __restrict__ out)
{
    __shared__ float4 sbuf[4][2][64];               // [warp][buf][f4]
    const int tid  = threadIdx.x;
    const int lane = tid & 31;
    const int warp = tid >> 5;
    const int g    = blockIdx.x * 4 + warp;         // global warp id
    const int row  = g >> 2;
    const int kb4  = (g & 3) * 512;                 // quarter offset in float4s

    const float4* w4 = (const float4*)(W_out + (size_t)row * D_INNER) + kb4;
    const float4* y4 = (const float4*)g_y + kb4;

    // Prime: chunks 0 and 1 (each thread copies 2 float4 per chunk).
    #pragma unroll
    for (int c = 0; c < 2; ++c) {
        __pipeline_memcpy_async(&sbuf[warp][c][lane],      &w4[c * 64 + lane],      16);
        __pipeline_memcpy_async(&sbuf[warp][c][lane + 32], &w4[c * 64 + lane + 32], 16);
        __pipeline_commit();
    }

    float acc0 = 0.0f, acc1 = 0.0f;
    #pragma unroll
    for (int c = 0; c < 8; ++c) {
        __pipeline_wait_prior(1);                   // chunk c landed
        float4 wa = sbuf[warp][c & 1][lane];
        float4 wb = sbuf[warp][c & 1][lane + 32];
        // refill this buffer with chunk c+2 (or empty group to keep counts)
        if (c < 6) {
            __pipeline_memcpy_async(&sbuf[warp][c & 1][lane],      &w4[(c + 2) * 64 + lane],      16);
            __pipeline_memcpy_async(&sbuf[warp][c & 1][lane + 32], &w4[(c + 2) * 64 + lane + 32], 16);
        }
        __pipeline_commit();
        float4 va = __ldg(&y4[c * 64 + lane]);
        float4 vb = __ldg(&y4[c * 64 + lane + 32]);
        acc0 = fmaf(wa.x, va.x, acc0); acc0 = fmaf(wa.y, va.y, acc0);
        acc0 = fmaf(wa.z, va.z, acc0); acc0 = fmaf(wa.w, va.w, acc0);
        acc1 = fmaf(wb.x, vb.x, acc1); acc1 = fmaf(wb.y, vb.y, acc1);
        acc1 = fmaf(wb.z, vb.z, acc1); acc1 = fmaf(wb.w, vb.w, acc1);
    }
    float acc = acc0 + acc1;
    #pragma unroll
    for (int o = 16; o; o >>= 1) acc += __shfl_xor_sync(0xffffffffu, acc, o);
    if (lane == 0) atomicAdd(&out[row], acc);
}

// ---------------------------------------------------------------------------
extern "C" void kernel_launch(void* const* d_in, const int* in_sizes, int n_in,
                              void* d_out, int out_size)
{
    const float* x           = (const float*)d_in[0];
    const float* ssm_state   = (const float*)d_in[1];
    const float* conv_buffer = (const float*)d_in[2];
    const float* W_in        = (const float*)d_in[3];
    const float* conv_w      = (const float*)d_in[4];
    const float* conv_b      = (const float*)d_in[5];
    const float* W_xp        = (const float*)d_in[6];
    const float* W_dt        = (const float*)d_in[7];
    const float* b_dt        = (const float*)d_in[8];
    const float* A_log       = (const float*)d_in[9];
    const float* D_param     = (const float*)d_in[10];
    const float* W_out       = (const float*)d_in[11];
    float* out = (float*)d_out;

    k_win <<<4096, 128>>>(W_in, x, conv_buffer, conv_w, conv_b, out);
    k_xp  <<<dim3(XP_DIM, D_INNER / KT_XP), 256>>>(W_xp);
    k_ssm <<<(D_INNER * D_STATE) / 256, 256>>>(W_dt, b_dt, ssm_state, A_log,
                                               D_param, out);
    k_wout<<<4096, 128>>>(W_out, out);
}

// round 15
// speedup vs baseline: 1.1359x; 1.0447x over previous
#include <cuda_runtime.h>
#include <math.h>

#define D_INNER 8192
#define D_MODEL 4096
#define DT_RANK 8
#define D_STATE 16
#define XP_DIM  (DT_RANK + 2 * D_STATE)   // 40

#define NB_XP    320                      // 40 rows x 8 K-chunks of 1024
#define NB_SSM   1024                     // 8 channels per block (16 lanes/ch)
#define NB_MID   (NB_XP + NB_SSM)         // 1344 — single wave (< 2368)

// Scratch + flag
__device__ float g_x_conv[D_INNER];
__device__ float g_z_silu[D_INNER];
__device__ float g_xp[XP_DIM];
__device__ float g_y[D_INNER];
__device__ unsigned int c_xp;

// ---------------------------------------------------------------------------
// Kernel 1: xz = W_in @ x (16384 x 4096) + fused conv/silu epilogue.
// Warp-per-row, 128thr, 16 blocks/SM. Blocks 0-31 zero out[0:4096];
// block 0 zeroes g_xp + resets c_xp. grid = 4096. (At BW ceiling.)
// ---------------------------------------------------------------------------
__global__ __launch_bounds__(128, 16) void k_win(
    const float* __restrict__ W_in,
    const float* __restrict__ x,
    const float* __restrict__ conv_buffer,
    const float* __restrict__ conv_w,
    const float* __restrict__ conv_b,
    float* __restrict__ out)
{
    const int tid  = threadIdx.x;
    const int lane = tid & 31;
    const int warp = tid >> 5;
    if (blockIdx.x < 32) out[blockIdx.x * 128 + tid] = 0.0f;
    if (blockIdx.x == 0) {
        if (tid < XP_DIM) g_xp[tid] = 0.0f;
        if (tid == 0) c_xp = 0;
    }

    const int row = blockIdx.x * 4 + warp;
    const float4* w4 = (const float4*)(W_in + (size_t)row * D_MODEL);
    const float4* x4 = (const float4*)x;

    float acc0 = 0.0f, acc1 = 0.0f;
    #pragma unroll
    for (int i = lane; i < D_MODEL / 4; i += 64) {
        float4 wa = __ldcs(&w4[i]);
        float4 wb = __ldcs(&w4[i + 32]);
        float4 va = x4[i];
        float4 vb = x4[i + 32];
        acc0 = fmaf(wa.x, va.x, acc0); acc0 = fmaf(wa.y, va.y, acc0);
        acc0 = fmaf(wa.z, va.z, acc0); acc0 = fmaf(wa.w, va.w, acc0);
        acc1 = fmaf(wb.x, vb.x, acc1); acc1 = fmaf(wb.y, vb.y, acc1);
        acc1 = fmaf(wb.z, vb.z, acc1); acc1 = fmaf(wb.w, vb.w, acc1);
    }
    float acc = acc0 + acc1;
    #pragma unroll
    for (int o = 16; o; o >>= 1) acc += __shfl_xor_sync(0xffffffffu, acc, o);

    if (lane == 0) {
        if (row < D_INNER) {
            float b1 = conv_buffer[row * 3 + 1];
            float b2 = conv_buffer[row * 3 + 2];
            float4 cw = ((const float4*)conv_w)[row];
            float s = fmaf(b1, cw.x, fmaf(b2, cw.y,
                       fmaf(acc, cw.z, fmaf(acc, cw.w, conv_b[row]))));
            g_x_conv[row] = s / (1.0f + __expf(-s));
        } else {
            g_z_silu[row - D_INNER] = acc / (1.0f + __expf(-acc));
        }
    }
}

// ---------------------------------------------------------------------------
// Kernel 2 (merged mid): xp GEMV (blocks 0-319) + SSM (blocks 320-1343).
// Single wave; ssm blocks prefetch ALL xp-independent operands into
// registers BEFORE spinning on c_xp, so the spin window still issues
// memory traffic. 16 lanes per channel, 8 channels per block.
// ---------------------------------------------------------------------------
__global__ __launch_bounds__(128, 16) void k_mid(
    const float* __restrict__ W_xp,
    const float* __restrict__ W_dt,
    const float* __restrict__ b_dt,
    const float* __restrict__ ssm_state,
    const float* __restrict__ A_log,
    const float* __restrict__ D_param,
    float* __restrict__ d_out)
{
    __shared__ float sh[XP_DIM];
    const int b   = blockIdx.x;
    const int tid = threadIdx.x;

    if (b < NB_XP) {
        // -------- xp = W_xp @ x_conv, split-K chunk (1024 cols) ------------
        const int row = b % XP_DIM;
        const int kb  = (b / XP_DIM) * 1024;
        const float4* w4 = (const float4*)(W_xp + (size_t)row * D_INNER + kb);
        const float4* v4 = (const float4*)(g_x_conv + kb);
        float acc = 0.0f;
        #pragma unroll
        for (int i = tid; i < 256; i += 128) {
            float4 w = __ldcs(&w4[i]);
            float4 v = v4[i];
            acc = fmaf(w.x, v.x, acc); acc = fmaf(w.y, v.y, acc);
            acc = fmaf(w.z, v.z, acc); acc = fmaf(w.w, v.w, acc);
        }
        #pragma unroll
        for (int o = 16; o; o >>= 1) acc += __shfl_xor_sync(0xffffffffu, acc, o);
        const int warp = tid >> 5, lane = tid & 31;
        if (lane == 0) sh[warp] = acc;
        __syncthreads();
        if (tid == 0) {
            atomicAdd(&g_xp[row], sh[0] + sh[1] + sh[2] + sh[3]);
            __threadfence();
            atomicAdd(&c_xp, 1u);
        }
    } else {
        // -------- SSM update: 8 channels/block, 16 lanes/channel -----------
        const int idx = b - NB_XP;               // 0..1023
        const int ch  = idx * 8 + (tid >> 4);    // channel
        const int s   = tid & 15;                // state index
        const int eidx = ch * D_STATE + s;

        // Prefetch everything that does NOT depend on xp.
        const float aval = A_log[eidx];
        const float sval = ssm_state[eidx];
        const float4* wd4 = (const float4*)(W_dt + (size_t)ch * DT_RANK);
        const float4 w0 = wd4[0], w1 = wd4[1];
        const float bdt  = b_dt[ch];
        const float xc   = g_x_conv[ch];
        const float zs   = g_z_silu[ch];
        const float dp   = D_param[ch];

        // Wait for xp completion (operands already in registers).
        if (tid == 0) {
            volatile unsigned int* p = &c_xp;
            while (*p < NB_XP) __nanosleep(128);
        }
        __syncthreads();
        __threadfence();
        if (tid < XP_DIM) sh[tid] = __ldcg(&g_xp[tid]);
        __syncthreads();

        float dtr = bdt;
        dtr = fmaf(w0.x, sh[0], dtr); dtr = fmaf(w0.y, sh[1], dtr);
        dtr = fmaf(w0.z, sh[2], dtr); dtr = fmaf(w0.w, sh[3], dtr);
        dtr = fmaf(w1.x, sh[4], dtr); dtr = fmaf(w1.y, sh[5], dtr);
        dtr = fmaf(w1.z, sh[6], dtr); dtr = fmaf(w1.w, sh[7], dtr);
        float dt = (dtr > 20.0f) ? dtr : log1pf(__expf(dtr));

        float A    = -__expf(aval);
        float abar = __expf(dt * A);
        float h    = fmaf(abar, sval, dt * sh[DT_RANK + s] * xc);
        d_out[D_MODEL + eidx] = h;

        float part = h * sh[DT_RANK + D_STATE + s];
        #pragma unroll
        for (int o = 8; o; o >>= 1) part += __shfl_xor_sync(0xffffffffu, part, o);
        if (s == 0)
            g_y[ch] = fmaf(dp, xc, part) * zs;
    }
}

// ---------------------------------------------------------------------------
// Kernel 3: out = W_out @ y (4096 x 8192). Warp per (row, K-quarter),
// 8KB contiguous stream per warp. grid = 4096. atomicAdd (out zeroed
// by k_win). (Best-known variant — R13.)
// ---------------------------------------------------------------------------
__global__ __launch_bounds__(128, 16) void k_wout(
    const float* __restrict__ W_out,
    float* __restrict__ out)
{
    const int tid  = threadIdx.x;
    const int lane = tid & 31;
    const int g    = blockIdx.x * 4 + (tid >> 5);   // global warp id
    const int row  = g >> 2;
    const int kb4  = (g & 3) * (D_INNER / 16);      // quarter offset in float4s

    const float4* w4 = (const float4*)(W_out + (size_t)row * D_INNER) + kb4;
    const float4* y4 = (const float4*)g_y + kb4;

    float acc0 = 0.0f, acc1 = 0.0f;
    #pragma unroll
    for (int i = lane; i < D_INNER / 16; i += 64) {
        float4 wa = __ldcs(&w4[i]);
        float4 wb = __ldcs(&w4[i + 32]);
        float4 va = y4[i];
        float4 vb = y4[i + 32];
        acc0 = fmaf(wa.x, va.x, acc0); acc0 = fmaf(wa.y, va.y, acc0);
        acc0 = fmaf(wa.z, va.z, acc0); acc0 = fmaf(wa.w, va.w, acc0);
        acc1 = fmaf(wb.x, vb.x, acc1); acc1 = fmaf(wb.y, vb.y, acc1);
        acc1 = fmaf(wb.z, vb.z, acc1); acc1 = fmaf(wb.w, vb.w, acc1);
    }
    float acc = acc0 + acc1;
    #pragma unroll
    for (int o = 16; o; o >>= 1) acc += __shfl_xor_sync(0xffffffffu, acc, o);
    if (lane == 0) atomicAdd(&out[row], acc);
}

// ---------------------------------------------------------------------------
extern "C" void kernel_launch(void* const* d_in, const int* in_sizes, int n_in,
                              void* d_out, int out_size)
{
    const float* x           = (const float*)d_in[0];
    const float* ssm_state   = (const float*)d_in[1];
    const float* conv_buffer = (const float*)d_in[2];
    const float* W_in        = (const float*)d_in[3];
    const float* conv_w      = (const float*)d_in[4];
    const float* conv_b      = (const float*)d_in[5];
    const float* W_xp        = (const float*)d_in[6];
    const float* W_dt        = (const float*)d_in[7];
    const float* b_dt        = (const float*)d_in[8];
    const float* A_log       = (const float*)d_in[9];
    const float* D_param     = (const float*)d_in[10];
    const float* W_out       = (const float*)d_in[11];
    float* out = (float*)d_out;

    k_win <<<4096, 128>>>(W_in, x, conv_buffer, conv_w, conv_b, out);
    k_mid <<<NB_MID, 128>>>(W_xp, W_dt, b_dt, ssm_state, A_log, D_param, out);
    k_wout<<<4096, 128>>>(W_out, out);
}